// round 14
// baseline (speedup 1.0000x reference)
#include <cuda_runtime.h>
#include <cuda_fp16.h>

typedef unsigned int u32;

__device__ __forceinline__ float tanh_fast(float x) {
    float y;
    asm("tanh.approx.f32 %0, %1;" : "=f"(y) : "f"(x));
    return y;
}
// Pack two f32 into f16x2: {hi16 = cvt(hi), lo16 = cvt(lo)}.
__device__ __forceinline__ u32 pkh2(float hi, float lo) {
    u32 d;
    asm("cvt.rn.f16x2.f32 %0, %1, %2;" : "=r"(d) : "f"(hi), "f"(lo));
    return d;
}
__device__ __forceinline__ float lo_h(u32 p) {
    __half2 h = *reinterpret_cast<__half2*>(&p);
    return __low2float(h);
}
__device__ __forceinline__ float hi_h(u32 p) {
    __half2 h = *reinterpret_cast<__half2*>(&p);
    return __high2float(h);
}

__device__ __forceinline__ void mma16816(float d[4],
    u32 a0, u32 a1, u32 a2, u32 a3, u32 b0, u32 b1,
    float c0, float c1, float c2, float c3)
{
    asm("mma.sync.aligned.m16n8k16.row.col.f32.f16.f16.f32 "
        "{%0,%1,%2,%3}, {%4,%5,%6,%7}, {%8,%9}, {%10,%11,%12,%13};"
        : "=f"(d[0]), "=f"(d[1]), "=f"(d[2]), "=f"(d[3])
        : "r"(a0), "r"(a1), "r"(a2), "r"(a3), "r"(b0), "r"(b1),
          "f"(c0), "f"(c1), "f"(c2), "f"(c3));
}

// Systolic 4-layer tanh RNN: ONE LAYER x 16 REAL batch rows per warp (full
// m16n8k16 utilization, 3 HMMA/warp-step). 1024 warps as 128 blocks x 256
// threads -> 2 warps on every SMSP of 128 SMs (R13 showed the HMMA pipe
// saturates at ~1 MMA / 15 cyc / SMSP; this spreads fully-used HMMAs over
// 2x the SMSPs of R13 and removes the 50% row duplication of R11).
//
// Warp w in block: layer = w>>1, group-in-block = w&1. Layer l at step i
// computes t = i - l from layer (l-1)'s step-(i-1) output. Hand-off is
// lane-aligned: producer's packed D (hh0,hh1,hl0,hl1) IS the consumer's
// input A-fragment (a2,a3 hi + lo), exchanged via double-buffered smem
// (uint4 per lane) with one __syncthreads per step (bar drains STS).
//
// f16 3-term split (precision verified 5.55e-5 in R13):
//   t1 = Ahh @ Whi + bias ; t2 = Ahh @ Wlo ; t3 = Ahl @ Whi  (parallel)
//   z = (t1 + t2) + t3
//
// STEP: HEADG = guard update for t<0 (i<layer); PFG = guard x prefetch vs T.
#define STEP(IVAL, U, HEADG, PFG)                                             \
    do {                                                                      \
        const int i_ = (IVAL);                                                \
        u32 ih0, ih1, il0, il1;                                               \
        if (l0) {                                                             \
            ih0 = xh0r[U]; ih1 = xh1r[U]; il0 = xl0r[U]; il1 = xl1r[U];       \
        } else {                                                              \
            const uint4 v = ex[i_ & 1][warp - 2][lane];                       \
            ih0 = v.x; ih1 = v.y; il0 = v.z; il1 = v.w;                       \
        }                                                                     \
        float t1[4], t2[4], t3[4];                                            \
        mma16816(t1, hh0, hh1, ih0, ih1, bwh0, bwh1, bc0, bc1, bc0, bc1);     \
        mma16816(t2, hh0, hh1, ih0, ih1, bwl0, bwl1, 0.f, 0.f, 0.f, 0.f);     \
        mma16816(t3, hl0, hl1, il0, il1, bwh0, bwh1, 0.f, 0.f, 0.f, 0.f);     \
        const float z0 = (t1[0] + t2[0]) + t3[0];                             \
        const float z1 = (t1[1] + t2[1]) + t3[1];                             \
        const float z2 = (t1[2] + t2[2]) + t3[2];                             \
        const float z3 = (t1[3] + t2[3]) + t3[3];                             \
        const bool upd = HEADG ? (i_ >= layer) : true;                        \
        if (upd) {                                                            \
            const float n0 = tanh_fast(z0);                                   \
            const float n1 = tanh_fast(z1);                                   \
            const float n2 = tanh_fast(z2);                                   \
            const float n3 = tanh_fast(z3);                                   \
            hh0 = pkh2(n1, n0); hh1 = pkh2(n3, n2);                           \
            hl0 = pkh2(n1 - hi_h(hh0), n0 - lo_h(hh0));                       \
            hl1 = pkh2(n3 - hi_h(hh1), n2 - lo_h(hh1));                       \
        }                                                                     \
        ex[(i_ + 1) & 1][warp][lane] = make_uint4(hh0, hh1, hl0, hl1);        \
        if (l0) {                                                             \
            float xv;                                                         \
            if (PFG) xv = ((i_ + 4) < T) ? __ldg(xp) : 0.0f;                  \
            else     xv = __ldg(xp);                                          \
            xp += B;                                                          \
            const float xa = __shfl_sync(0xffffffffu, xv, grp);               \
            const float xb = __shfl_sync(0xffffffffu, xv, grp + 8);           \
            const u32 p0 = pkh2(0.f, xa), p1 = pkh2(0.f, xb);                 \
            xh0r[U] = p0; xh1r[U] = p1;                                       \
            xl0r[U] = pkh2(0.f, xa - lo_h(p0));                               \
            xl1r[U] = pkh2(0.f, xb - lo_h(p1));                               \
        }                                                                     \
        __syncthreads();                                                      \
    } while (0)

__global__ void __launch_bounds__(256, 1) rnnls_kernel(
    const float* __restrict__ x,        // [T, B]
    const float* __restrict__ h0,       // [4, B, 8]
    const float* __restrict__ W_ih0,    // [8, 1]
    const float* __restrict__ W_ih_rest,// [3, 8, 8]
    const float* __restrict__ W_hh,     // [4, 8, 8]
    const float* __restrict__ b_ih,     // [4, 8]
    const float* __restrict__ b_hh,     // [4, 8]
    const float* __restrict__ W_out,    // [1, 8]
    const float* __restrict__ b_out,    // [1]
    float* __restrict__ out,            // [B]
    int T, int B)
{
    // Double-buffered per-warp exchange: [parity][warp][lane] 16B slots = 8KB.
    __shared__ uint4 ex[2][8][32];

    const int tid   = threadIdx.x;
    const int warp  = tid >> 5;          // 0..7
    const int lane  = tid & 31;
    const int layer = warp >> 1;         // 0..3
    const int gi    = warp & 1;          // group within block
    const int b0    = (blockIdx.x * 2 + gi) * 16;   // 16 real batch rows
    const int grp   = lane >> 2;         // fragment row group (0..7)
    const int c     = lane & 3;
    const int j0    = 2 * c;             // output-unit column base
    const bool l0   = (layer == 0);

    // B fragment for this layer: k = j0,j0+1 -> W_hh (own h); k = 8+j0.. ->
    // W_ih (input). Column n = grp. Split into f16 hi + lo.
    u32 bwh0, bwh1, bwl0, bwl1;
    float bc0, bc1;
    {
        const float w0 = W_hh[(layer * 8 + grp) * 8 + j0];
        const float w1 = W_hh[(layer * 8 + grp) * 8 + j0 + 1];
        float v0, v1;
        if (l0) { v0 = (c == 0) ? W_ih0[grp] : 0.0f; v1 = 0.0f; }
        else {
            v0 = W_ih_rest[((layer - 1) * 8 + grp) * 8 + j0];
            v1 = W_ih_rest[((layer - 1) * 8 + grp) * 8 + j0 + 1];
        }
        const u32 ph = pkh2(w1, w0);
        const u32 pv = pkh2(v1, v0);
        bwh0 = ph; bwh1 = pv;
        bwl0 = pkh2(w1 - hi_h(ph), w0 - lo_h(ph));
        bwl1 = pkh2(v1 - hi_h(pv), v0 - lo_h(pv));
        bc0 = b_ih[layer * 8 + j0] + b_hh[layer * 8 + j0];
        bc1 = b_ih[layer * 8 + j0 + 1] + b_hh[layer * 8 + j0 + 1];
    }

    // Own h state: rows b0+grp (hh0/hl0) and b0+grp+8 (hh1/hl1), units j0,j0+1.
    u32 hh0, hh1, hl0, hl1;
    {
        const float a0 = h0[((size_t)(layer * B + b0 + grp)) * 8 + j0];
        const float a1 = h0[((size_t)(layer * B + b0 + grp)) * 8 + j0 + 1];
        const float a2 = h0[((size_t)(layer * B + b0 + grp + 8)) * 8 + j0];
        const float a3 = h0[((size_t)(layer * B + b0 + grp + 8)) * 8 + j0 + 1];
        hh0 = pkh2(a1, a0); hh1 = pkh2(a3, a2);
        hl0 = pkh2(a1 - hi_h(hh0), a0 - lo_h(hh0));
        hl1 = pkh2(a3 - hi_h(hh1), a2 - lo_h(hh1));
    }

    // Seed parity-0 buffer with h0 so consumers' step-0 reads see it.
    ex[0][warp][lane] = make_uint4(hh0, hh1, hl0, hl1);

    // x prefetch ring (layer-0 warps only): lanes 0..15 carry rows 0..15;
    // slots pre-shuffled/pre-packed into A-fragment form (hi + residual).
    const int xlane = lane & 15;
    const float* xp = x + b0 + xlane;
    u32 xh0r[4], xh1r[4], xl0r[4], xl1r[4];
    if (l0) {
        #pragma unroll
        for (int p = 0; p < 4; ++p) {
            const float xv = (p < T) ? __ldg(xp) : 0.0f;
            xp += B;
            const float xa = __shfl_sync(0xffffffffu, xv, grp);
            const float xb = __shfl_sync(0xffffffffu, xv, grp + 8);
            const u32 p0 = pkh2(0.f, xa), p1 = pkh2(0.f, xb);
            xh0r[p] = p0; xh1r[p] = p1;
            xl0r[p] = pkh2(0.f, xa - lo_h(p0));
            xl1r[p] = pkh2(0.f, xb - lo_h(p1));
        }
    }
    __syncthreads();

    // Head: 4 steps with t<0 guard (layer l starts updating at step l).
    STEP(0, 0, true, true);
    STEP(1, 1, true, true);
    STEP(2, 2, true, true);
    STEP(3, 3, true, true);

    // Main: unguarded prefetch (i+4 <= T-1 guaranteed by bound).
    const int main_end = (T - 4) & ~3;
    for (int io = 4; io < main_end; io += 4) {
        STEP(io + 0, 0, false, false);
        STEP(io + 1, 1, false, false);
        STEP(io + 2, 2, false, false);
        STEP(io + 3, 3, false, false);
    }

    // Epilogue: guarded prefetch; post-T outputs of layers 0-2 are unused
    // and finite; layer 3's last update lands exactly at t = T-1.
    const int NITER = T + 3;
    for (int i = main_end; i < NITER; ++i)
        STEP(i, i & 3, false, true);

    // Readout: layer-3 warps hold h(T-1) for rows b0+grp, b0+grp+8.
    if (layer == 3) {
        const float h00 = lo_h(hh0) + lo_h(hl0);
        const float h01 = hi_h(hh0) + hi_h(hl0);
        const float h10 = lo_h(hh1) + lo_h(hl1);
        const float h11 = hi_h(hh1) + hi_h(hl1);
        const float w0 = W_out[j0], w1 = W_out[j0 + 1];
        float pr0 = h00 * w0 + h01 * w1;
        float pr1 = h10 * w0 + h11 * w1;
        pr0 += __shfl_xor_sync(0xffffffffu, pr0, 1);
        pr0 += __shfl_xor_sync(0xffffffffu, pr0, 2);
        pr1 += __shfl_xor_sync(0xffffffffu, pr1, 1);
        pr1 += __shfl_xor_sync(0xffffffffu, pr1, 2);
        if (c == 0) {
            const float bo = b_out[0];
            out[b0 + grp]     = pr0 + bo;
            out[b0 + grp + 8] = pr1 + bo;
        }
    }
}

extern "C" void kernel_launch(void* const* d_in, const int* in_sizes, int n_in,
                              void* d_out, int out_size) {
    const float* x         = (const float*)d_in[0];
    const float* h0        = (const float*)d_in[1];
    const float* W_ih0     = (const float*)d_in[2];
    const float* W_ih_rest = (const float*)d_in[3];
    const float* W_hh      = (const float*)d_in[4];
    const float* b_ih      = (const float*)d_in[5];
    const float* b_hh      = (const float*)d_in[6];
    const float* W_out     = (const float*)d_in[7];
    const float* b_out     = (const float*)d_in[8];

    const int B = in_sizes[1] / 32;   // h0: [4, B, 8]
    const int T = in_sizes[0] / B;    // x:  [T, B, 1]

    // 16 rows x 4 layer-warps per group; 2 groups per 256-thread block.
    // B = 4096 -> 256 groups -> 128 blocks (B must be a multiple of 32).
    const int grid = B / 32;

    rnnls_kernel<<<grid, 256>>>(x, h0, W_ih0, W_ih_rest, W_hh, b_ih, b_hh,
                                W_out, b_out, (float*)d_out, T, B);
}

// round 16
// speedup vs baseline: 3.2762x; 3.2762x over previous
#include <cuda_runtime.h>
#include <cuda_fp16.h>

typedef unsigned int u32;

__device__ __forceinline__ float tanh_fast(float x) {
    float y;
    asm("tanh.approx.f32 %0, %1;" : "=f"(y) : "f"(x));
    return y;
}
// Pack two f32 into f16x2: {hi16 = cvt(hi), lo16 = cvt(lo)}.
__device__ __forceinline__ u32 pkh2(float hi, float lo) {
    u32 d;
    asm("cvt.rn.f16x2.f32 %0, %1, %2;" : "=r"(d) : "f"(hi), "f"(lo));
    return d;
}
__device__ __forceinline__ float lo_h(u32 p) {
    __half2 h = *reinterpret_cast<__half2*>(&p);
    return __low2float(h);
}
__device__ __forceinline__ float hi_h(u32 p) {
    __half2 h = *reinterpret_cast<__half2*>(&p);
    return __high2float(h);
}

// d = A@B + c  (fresh accumulator from C inputs)
__device__ __forceinline__ void mma16816(float d[4],
    u32 a0, u32 a1, u32 a2, u32 a3, u32 b0, u32 b1,
    float c0, float c1, float c2, float c3)
{
    asm("mma.sync.aligned.m16n8k16.row.col.f32.f16.f16.f32 "
        "{%0,%1,%2,%3}, {%4,%5,%6,%7}, {%8,%9}, {%10,%11,%12,%13};"
        : "=f"(d[0]), "=f"(d[1]), "=f"(d[2]), "=f"(d[3])
        : "r"(a0), "r"(a1), "r"(a2), "r"(a3), "r"(b0), "r"(b1),
          "f"(c0), "f"(c1), "f"(c2), "f"(c3));
}
// d += A@B  (in-place accumulate: D and C alias the same registers).
__device__ __forceinline__ void mma16816_acc(float d[4],
    u32 a0, u32 a1, u32 a2, u32 a3, u32 b0, u32 b1)
{
    asm("mma.sync.aligned.m16n8k16.row.col.f32.f16.f16.f32 "
        "{%0,%1,%2,%3}, {%4,%5,%6,%7}, {%8,%9}, {%0,%1,%2,%3};"
        : "+f"(d[0]), "+f"(d[1]), "+f"(d[2]), "+f"(d[3])
        : "r"(a0), "r"(a1), "r"(a2), "r"(a3), "r"(b0), "r"(b1));
}

// Systolic 4-layer tanh RNN on tensor cores, 8 batch rows per warp, with the
// fragment's UPPER 8 rows carrying the hi/lo RESIDUALS instead of duplicates:
//   A rows 0-7  = [hh | in_hi]   (a0 = hh,   a2 = input hi)
//   A rows 8-15 = [hl | in_lo]   (a1 = hl,   a3 = input lo)
//   MMA1: B = [Whi; Wi_hi] + bias;  MMA2 (C-chained in-place): B = [Wlo; Wi_lo]
//   z = d0 + d2  ->  EXACT fp32-accumulated product of split h and split W
//   (all four cross terms incl. lo*lo), at R11's cost: 8 HMMA/step.
// Error 2x2 (R11/R13/R15): both W-split and h-split are required; this gets
// both for free via row-packing. 512 warps, 1 warp/SMSP on 128 SMs.
//
// UPDL guarded by HEADN for the 4 head steps (t<0 lanes must keep h0).
#define UPDL(L, M, HEADN)                                                     \
    do { if ((L) < (HEADN)) {                                                 \
        const float z0 = (M)[0] + (M)[2];                                     \
        const float z1 = (M)[1] + (M)[3];                                     \
        const float t0 = tanh_fast(z0);                                       \
        const float t1 = tanh_fast(z1);                                       \
        const u32 n0 = pkh2(t1, t0);                                          \
        hl[L] = pkh2(t1 - hi_h(n0), t0 - lo_h(n0));                           \
        hh[L] = n0;                                                           \
    } } while (0)

// Prefetch + pre-shuffle + pre-pack x (hi + residual) for step (i+4).
#define XPF(U, GUARDED, IVAL)                                                 \
    do {                                                                      \
        float xv;                                                             \
        if (GUARDED) xv = (((IVAL) + 4) < T) ? __ldg(xp) : 0.0f;              \
        else         xv = __ldg(xp);                                          \
        xp += B;                                                              \
        const float xa = __shfl_sync(0xffffffffu, xv, grp);                   \
        const u32 h_ = pkh2(0.f, xa);                                         \
        xhr[U] = h_;                                                          \
        xlr[U] = pkh2(0.f, xa - lo_h(h_));                                    \
    } while (0)

#define STEP(IVAL, U, HEADN, PFG)                                             \
    do {                                                                      \
        const u32 xh = xhr[U], xl = xlr[U];                                   \
        float m0[4], m1[4], m2[4], m3[4];                                     \
        /* MMA1 per layer: [hh|in_hi ; hl|in_lo] @ [Whi; Wi_hi] + bias */     \
        mma16816(m0, hh[0], hl[0], xh,    xl,    bwh[0][0], bwh[0][1],        \
                 biasc[0][0], biasc[0][1], 0.f, 0.f);                         \
        mma16816(m1, hh[1], hl[1], hh[0], hl[0], bwh[1][0], bwh[1][1],        \
                 biasc[1][0], biasc[1][1], 0.f, 0.f);                         \
        mma16816(m2, hh[2], hl[2], hh[1], hl[1], bwh[2][0], bwh[2][1],        \
                 biasc[2][0], biasc[2][1], 0.f, 0.f);                         \
        mma16816(m3, hh[3], hl[3], hh[2], hl[2], bwh[3][0], bwh[3][1],        \
                 biasc[3][0], biasc[3][1], 0.f, 0.f);                         \
        /* MMA2: same A, B = [Wlo; Wi_lo], C-chained in place */              \
        mma16816_acc(m0, hh[0], hl[0], xh,    xl,    bwl[0][0], bwl[0][1]);   \
        mma16816_acc(m1, hh[1], hl[1], hh[0], hl[0], bwl[1][0], bwl[1][1]);   \
        mma16816_acc(m2, hh[2], hl[2], hh[1], hl[1], bwl[2][0], bwl[2][1]);   \
        mma16816_acc(m3, hh[3], hl[3], hh[2], hl[2], bwl[3][0], bwl[3][1]);   \
        UPDL(0, m0, HEADN);                                                   \
        UPDL(1, m1, HEADN);                                                   \
        UPDL(2, m2, HEADN);                                                   \
        UPDL(3, m3, HEADN);                                                   \
        XPF(U, PFG, IVAL);                                                    \
    } while (0)

__global__ void __launch_bounds__(128, 1) rnnrp_kernel(
    const float* __restrict__ x,        // [T, B]
    const float* __restrict__ h0,       // [4, B, 8]
    const float* __restrict__ W_ih0,    // [8, 1]
    const float* __restrict__ W_ih_rest,// [3, 8, 8]
    const float* __restrict__ W_hh,     // [4, 8, 8]
    const float* __restrict__ b_ih,     // [4, 8]
    const float* __restrict__ b_hh,     // [4, 8]
    const float* __restrict__ W_out,    // [1, 8]
    const float* __restrict__ b_out,    // [1]
    float* __restrict__ out,            // [B]
    int T, int B)
{
    const int warp = threadIdx.x >> 5;
    const int lane = threadIdx.x & 31;
    const int b0   = (blockIdx.x * 4 + warp) * 8;   // 8 real batch rows/warp
    if (b0 >= B) return;
    const int grp = lane >> 2;   // fragment row group (0..7) = real row
    const int c   = lane & 3;    // thread-in-group
    const int j0  = 2 * c;       // output-unit column base

    // B fragments (col-major k16 x n8): lane holds k = j0,j0+1 (Wh, k<8) and
    // k = 8+j0, 9+j0 (Wi) at column n = grp. W split into f16 hi + f16 lo.
    u32 bwh[4][2], bwl[4][2];
    float biasc[4][2];
    #pragma unroll
    for (int l = 0; l < 4; ++l) {
        const float w0 = W_hh[(l * 8 + grp) * 8 + j0];
        const float w1 = W_hh[(l * 8 + grp) * 8 + j0 + 1];
        float v0, v1;
        if (l == 0) { v0 = (c == 0) ? W_ih0[grp] : 0.0f; v1 = 0.0f; }
        else {
            v0 = W_ih_rest[((l - 1) * 8 + grp) * 8 + j0];
            v1 = W_ih_rest[((l - 1) * 8 + grp) * 8 + j0 + 1];
        }
        const u32 ph = pkh2(w1, w0);
        const u32 pv = pkh2(v1, v0);
        bwh[l][0] = ph;
        bwh[l][1] = pv;
        bwl[l][0] = pkh2(w1 - hi_h(ph), w0 - lo_h(ph));
        bwl[l][1] = pkh2(v1 - hi_h(pv), v0 - lo_h(pv));
        biasc[l][0] = b_ih[l * 8 + j0] + b_hh[l * 8 + j0];
        biasc[l][1] = b_ih[l * 8 + j0 + 1] + b_hh[l * 8 + j0 + 1];
    }

    // h state: f16x2 hi + f16x2 lo per layer (units j0, j0+1 of row grp).
    u32 hh[4], hl[4];
    #pragma unroll
    for (int l = 0; l < 4; ++l) {
        const float v0 = h0[((size_t)(l * B + b0 + grp)) * 8 + j0];
        const float v1 = h0[((size_t)(l * B + b0 + grp)) * 8 + j0 + 1];
        const u32 p0 = pkh2(v1, v0);
        hh[l] = p0;
        hl[l] = pkh2(v1 - hi_h(p0), v0 - lo_h(p0));
    }

    // x prefetch ring, pre-shuffled/pre-packed (hi + residual).
    const int xlane = lane & 7;
    const float* xp = x + b0 + xlane;
    u32 xhr[4], xlr[4];
    #pragma unroll
    for (int p = 0; p < 4; ++p) {
        const float xv = (p < T) ? __ldg(xp) : 0.0f;
        xp += B;
        const float xa = __shfl_sync(0xffffffffu, xv, grp);
        const u32 h_ = pkh2(0.f, xa);
        xhr[p] = h_;
        xlr[p] = pkh2(0.f, xa - lo_h(h_));
    }

    // Head: 4 steps; layer l starts updating at step l.
    STEP(0, 0, 1, true);
    STEP(1, 1, 2, true);
    STEP(2, 2, 3, true);
    STEP(3, 3, 4, true);

    // Main: unguarded prefetch (i+4 <= T-1 guaranteed by bound).
    const int main_end = (T - 4) & ~3;
    for (int io = 4; io < main_end; io += 4) {
        STEP(io + 0, 0, 4, false);
        STEP(io + 1, 1, 4, false);
        STEP(io + 2, 2, 4, false);
        STEP(io + 3, 3, 4, false);
    }

    // Epilogue: guarded prefetch; post-T outputs of layers 0-2 are unused
    // and finite; layer 3's last update lands exactly at t = T-1.
    const int NITER = T + 3;
    for (int i = main_end; i < NITER; ++i)
        STEP(i, i & 3, 4, true);

    // Readout: layer 3 h(T-1); lane holds units j0, j0+1 of row b0+grp.
    {
        const float h00 = lo_h(hh[3]) + lo_h(hl[3]);
        const float h01 = hi_h(hh[3]) + hi_h(hl[3]);
        float pr = h00 * W_out[j0] + h01 * W_out[j0 + 1];
        pr += __shfl_xor_sync(0xffffffffu, pr, 1);
        pr += __shfl_xor_sync(0xffffffffu, pr, 2);
        if (c == 0)
            out[b0 + grp] = pr + b_out[0];
    }
}

extern "C" void kernel_launch(void* const* d_in, const int* in_sizes, int n_in,
                              void* d_out, int out_size) {
    const float* x         = (const float*)d_in[0];
    const float* h0        = (const float*)d_in[1];
    const float* W_ih0     = (const float*)d_in[2];
    const float* W_ih_rest = (const float*)d_in[3];
    const float* W_hh      = (const float*)d_in[4];
    const float* b_ih      = (const float*)d_in[5];
    const float* b_hh      = (const float*)d_in[6];
    const float* W_out     = (const float*)d_in[7];
    const float* b_out     = (const float*)d_in[8];

    const int B = in_sizes[1] / 32;   // h0: [4, B, 8]
    const int T = in_sizes[0] / B;    // x:  [T, B, 1]

    // 8 real rows per warp -> B/8 warps; block 128 = 4 warps (one per SMSP).
    const int nwarps = (B + 7) / 8;
    const int grid   = (nwarps + 3) / 4;

    rnnrp_kernel<<<grid, 128>>>(x, h0, W_ih0, W_ih_rest, W_hh, b_ih, b_hh,
                                W_out, b_out, (float*)d_out, T, B);
}